// round 6
// baseline (speedup 1.0000x reference)
#include <cuda_runtime.h>
#include <cuda_bf16.h>

#define BQ 256
#define DD 256
#define NBANK 100000
#define NPAD 100096                    // padded rows (zero tail, safe cp.async)
#define TN 128
#define NUM_TILES ((NBANK + TN - 1) / TN)
#define NCH 8                          // K chunks of 32
#define KCH 32
#define SR 80                          // smem row stride bytes (64B data + 16B pad; 16B aligned!)

typedef unsigned long long ull;
typedef unsigned int u32;

// --------------- device scratch (no allocation allowed) ---------------------
__device__ ull   g_bestP[BQ];
__device__ ull   g_bestF[BQ];
__device__ uint4 g_Q[NCH][2][BQ][4];           // pre-split queries (256KB, L2-resident)
__device__ uint4 g_bankH[(size_t)NPAD * 32];   // bf16 hi image [n][256]
__device__ uint4 g_bankL[(size_t)NPAD * 32];   // bf16 lo image [n][256]
__device__ float g_b2[NPAD];

// --------------- smem layout (bytes) ----------------------------------------
#define QBUF  (2 * BQ * SR)                  // 40960 per buffer (hi+lo)
#define BBUF  (2 * TN * SR)                  // 20480 per buffer (hi+lo)
#define OFF_Q    0                           // [2 buf][2 split][256][SR]
#define OFF_B    (2 * QBUF)                  // 81920: [2 buf][2 split][128][SR]
#define OFF_RED  (OFF_B + 2 * BBUF)          // 122880
#define OFF_B2S  (OFF_RED + 2 * BQ * 8)      // 126976
#define OFF_SCLU (OFF_B2S + 512)
#define OFF_SCLS (OFF_SCLU + 512)
#define OFF_SCID (OFF_SCLS + 512)
#define OFF_SGT  (OFF_SCID + 1024)
#define SMEM_TOTAL (OFF_SGT + 1024)          // 130560

// --------------- helpers ------------------------------------------------------
__device__ __forceinline__ u32 smem_u32(const void* p) {
    u32 a;
    asm("{ .reg .u64 t; cvta.to.shared.u64 t, %1; cvt.u32.u64 %0, t; }" : "=r"(a) : "l"(p));
    return a;
}

#define LDSM_X4(r, addr) \
    asm volatile("ldmatrix.sync.aligned.m8n8.x4.shared.b16 {%0,%1,%2,%3}, [%4];" \
        : "=r"((r)[0]), "=r"((r)[1]), "=r"((r)[2]), "=r"((r)[3]) : "r"(addr))

#define MMA16816(d, a, b0, b1) \
    asm volatile("mma.sync.aligned.m16n8k16.row.col.f32.bf16.bf16.f32 " \
        "{%0,%1,%2,%3}, {%4,%5,%6,%7}, {%8,%9}, {%0,%1,%2,%3};" \
        : "+f"((d)[0]), "+f"((d)[1]), "+f"((d)[2]), "+f"((d)[3]) \
        : "r"((a)[0]), "r"((a)[1]), "r"((a)[2]), "r"((a)[3]), "r"(b0), "r"(b1))

#define CP_ASYNC16(dst, src) \
    asm volatile("cp.async.cg.shared.global [%0], [%1], 16;" :: "r"(dst), "l"(src) : "memory")
#define CP_COMMIT() asm volatile("cp.async.commit_group;" ::: "memory")
#define CP_WAIT0()  asm volatile("cp.async.wait_group 0;" ::: "memory")

// order-preserving float->u32 packed with index; ties -> lower index (argmin)
__device__ __forceinline__ ull encode(float f, int n) {
    u32 u = __float_as_uint(f);
    u = (u & 0x80000000u) ? ~u : (u | 0x80000000u);
    return ((ull)u << 32) | (u32)n;
}

__device__ __forceinline__ void split2(float a0, float a1, u32& H, u32& L) {
    __nv_bfloat16 h0 = __float2bfloat16(a0);
    __nv_bfloat16 h1 = __float2bfloat16(a1);
    __nv_bfloat16 l0 = __float2bfloat16(a0 - __bfloat162float(h0));
    __nv_bfloat16 l1 = __float2bfloat16(a1 - __bfloat162float(h1));
    H = (u32)__bfloat16_as_ushort(h0) | ((u32)__bfloat16_as_ushort(h1) << 16);
    L = (u32)__bfloat16_as_ushort(l0) | ((u32)__bfloat16_as_ushort(l1) << 16);
}

// ---------------------------------------------------------------------------
// prep: reset best arrays, split queries into bf16 hi/lo chunk images.
// ---------------------------------------------------------------------------
__global__ void prep_kernel(const float* __restrict__ feat) {
    int q = threadIdx.x;
    g_bestP[q] = ~0ULL;
    g_bestF[q] = ~0ULL;
    const float* row = feat + q * DD;
#pragma unroll
    for (int c = 0; c < NCH; ++c) {
#pragma unroll
        for (int i = 0; i < 4; ++i) {
            u32 H[4], L[4];
#pragma unroll
            for (int e = 0; e < 8; e += 2) {
                int k = c * KCH + i * 8 + e;
                split2(row[k], row[k + 1], H[e >> 1], L[e >> 1]);
            }
            g_Q[c][0][q][i] = make_uint4(H[0], H[1], H[2], H[3]);
            g_Q[c][1][q][i] = make_uint4(L[0], L[1], L[2], L[3]);
        }
    }
}

// ---------------------------------------------------------------------------
// convert: bank fp32 -> bf16 hi/lo global images + row norms. One warp per row.
// ---------------------------------------------------------------------------
__global__ void __launch_bounds__(256) convert_kernel(const float* __restrict__ bank) {
    int row = blockIdx.x * 8 + (threadIdx.x >> 5);
    if (row >= NBANK) return;
    int lane = threadIdx.x & 31;
    const float4* src = (const float4*)(bank + (size_t)row * DD) + lane * 2;
    float4 v0 = src[0], v1 = src[1];
    float vv[8] = {v0.x, v0.y, v0.z, v0.w, v1.x, v1.y, v1.z, v1.w};
    u32 H[4], L[4];
    float s = 0.f;
#pragma unroll
    for (int e = 0; e < 8; e += 2) {
        s = fmaf(vv[e], vv[e], s);
        s = fmaf(vv[e + 1], vv[e + 1], s);
        split2(vv[e], vv[e + 1], H[e >> 1], L[e >> 1]);
    }
    g_bankH[(size_t)row * 32 + lane] = make_uint4(H[0], H[1], H[2], H[3]);
    g_bankL[(size_t)row * 32 + lane] = make_uint4(L[0], L[1], L[2], L[3]);
#pragma unroll
    for (int o = 16; o; o >>= 1) s += __shfl_xor_sync(0xffffffffu, s, o);
    if (lane == 0) g_b2[row] = s;
}

// ---------------------------------------------------------------------------
__device__ __forceinline__ void stage_chunk(u32 smb, int buf, int c, int tid, int n0) {
    // Q: thread tid stages query row tid, both splits (8x16B)
    {
        const uint4* sH = &g_Q[c][0][tid][0];
        const uint4* sL = &g_Q[c][1][tid][0];
        u32 dH = smb + OFF_Q + (u32)buf * QBUF + (u32)tid * SR;
        u32 dL = dH + (u32)BQ * SR;
#pragma unroll
        for (int i = 0; i < 4; ++i) {
            CP_ASYNC16(dH + 16 * i, sH + i);
            CP_ASYNC16(dL + 16 * i, sL + i);
        }
    }
    // B: 1024 pieces (2 splits x 128 rows x 4 segs) / 256 threads = 4 each
#pragma unroll
    for (int p = 0; p < 4; ++p) {
        int idx = tid + 256 * p;
        int split = idx >> 9, rw = (idx >> 2) & 127, seg = idx & 3;
        const uint4* src = (split ? g_bankL : g_bankH)
                           + (size_t)(n0 + rw) * 32 + c * 4 + seg;
        u32 dst = smb + OFF_B + (u32)buf * BBUF + (u32)split * (TN * SR)
                  + (u32)rw * SR + (u32)seg * 16;
        CP_ASYNC16(dst, src);
    }
}

// ---------------------------------------------------------------------------
// main: 128 bank rows x 256 queries per CTA; 3-split bf16 HMMA GEMM,
// cp.async double-buffered A and B chunks, masked dual argmin epilogue.
// ---------------------------------------------------------------------------
__global__ void __launch_bounds__(256, 1) main_kernel(
    const int* __restrict__ cluL, const int* __restrict__ clsL,
    const int* __restrict__ cid,  const int* __restrict__ gt)
{
    extern __shared__ char sm[];
    const u32 smb  = smem_u32(sm);
    const int tid  = threadIdx.x;
    const int lane = tid & 31;
    const int w    = tid >> 5;
    const int n0   = blockIdx.x * TN;

    ull*   redP = (ull*)(sm + OFF_RED);
    ull*   redF = redP + BQ;
    float* b2s  = (float*)(sm + OFF_B2S);
    int*   sClu = (int*)(sm + OFF_SCLU);
    int*   sCls = (int*)(sm + OFF_SCLS);
    int*   sCid = (int*)(sm + OFF_SCID);
    int*   sGt  = (int*)(sm + OFF_SGT);

    stage_chunk(smb, 0, 0, tid, n0);
    CP_COMMIT();

    redP[tid] = ~0ULL;
    redF[tid] = ~0ULL;
    sCid[tid] = cid[tid];
    sGt[tid]  = gt[tid];
    if (tid < TN) {
        int n = n0 + tid;
        bool v = (n < NBANK);
        sClu[tid] = v ? cluL[n] : -1;
        sCls[tid] = v ? clsL[n] : 0x7fffffff;
        b2s[tid]  = v ? g_b2[n] : 0.f;
    }

    // Warp tiling: 4 q-groups x 2 n-halves. 64q x 64n per warp.
    const int q0 = (w & 3) * 64;
    const int nh = (w >> 2) * 64;

    float acc[4][8][4];
#pragma unroll
    for (int mi = 0; mi < 4; mi++)
#pragma unroll
        for (int nt = 0; nt < 8; nt++)
#pragma unroll
            for (int r = 0; r < 4; r++) acc[mi][nt][r] = 0.f;

    const u32 aRowOff = (u32)(q0 + (lane & 15)) * SR + (u32)(lane >> 4) * 16;
    const int bRow    = nh + ((lane >> 4) & 1) * 8 + (lane & 7);
    const u32 bColB   = ((lane >> 3) & 1) * 16;      // k-half byte offset

#pragma unroll 1
    for (int c = 0; c < NCH; ++c) {
        CP_WAIT0();
        __syncthreads();                              // chunk c resident
        if (c + 1 < NCH) { stage_chunk(smb, (c + 1) & 1, c + 1, tid, n0); CP_COMMIT(); }

        const int buf = c & 1;
        const u32 qH = smb + OFF_Q + (u32)buf * QBUF + aRowOff;
        const u32 qL = qH + (u32)BQ * SR;
        const u32 bH = smb + OFF_B + (u32)buf * BBUF;
        const u32 bL = bH + (u32)(TN * SR);
#pragma unroll
        for (int kk = 0; kk < KCH; kk += 16) {
            const u32 kb = (u32)kk * 2 + bColB;
            u32 aH[4][4];
#pragma unroll
            for (int mi = 0; mi < 4; mi++) LDSM_X4(aH[mi], qH + mi * 16 * SR + kk * 2);

            u32 bB[16];
#pragma unroll
            for (int p = 0; p < 4; p++)
                LDSM_X4(&bB[4 * p], bH + (u32)(bRow + p * 16) * SR + kb);
#pragma unroll
            for (int mi = 0; mi < 4; mi++)
#pragma unroll
                for (int nt = 0; nt < 8; nt++)
                    MMA16816(acc[mi][nt], aH[mi], bB[2 * nt], bB[2 * nt + 1]);

            u32 aL[4][4];
#pragma unroll
            for (int mi = 0; mi < 4; mi++) LDSM_X4(aL[mi], qL + mi * 16 * SR + kk * 2);
#pragma unroll
            for (int mi = 0; mi < 4; mi++)
#pragma unroll
                for (int nt = 0; nt < 8; nt++)
                    MMA16816(acc[mi][nt], aL[mi], bB[2 * nt], bB[2 * nt + 1]);

#pragma unroll
            for (int p = 0; p < 4; p++)
                LDSM_X4(&bB[4 * p], bL + (u32)(bRow + p * 16) * SR + kb);
#pragma unroll
            for (int mi = 0; mi < 4; mi++)
#pragma unroll
                for (int nt = 0; nt < 8; nt++)
                    MMA16816(acc[mi][nt], aH[mi], bB[2 * nt], bB[2 * nt + 1]);
        }
    }

    // ---- epilogue: masked dual argmin from HMMA fragments ----
    {
        const int jb = nh + 2 * (lane & 3);
        float b2r[16]; int clsr[16], clur[16]; bool val[16];
#pragma unroll
        for (int ni = 0; ni < 8; ni++)
#pragma unroll
            for (int h = 0; h < 2; h++) {
                int j = jb + 8 * ni + h, x = ni * 2 + h;
                b2r[x]  = b2s[j];
                clsr[x] = sCls[j];
                clur[x] = sClu[j];
                val[x]  = (n0 + j) < NBANK;
            }
#pragma unroll
        for (int mi = 0; mi < 4; mi++) {
#pragma unroll
            for (int half = 0; half < 2; half++) {
                int r = q0 + mi * 16 + (lane >> 2) + 8 * half;
                int gtq = sGt[r], ciq = sCid[r];
                ull bp = ~0ULL, bf = ~0ULL;
#pragma unroll
                for (int ni = 0; ni < 8; ni++)
#pragma unroll
                    for (int h = 0; h < 2; h++) {
                        int x = ni * 2 + h;
                        if (!val[x] || clsr[x] == gtq) continue;
                        float score = fmaf(-2.f, acc[mi][ni][half * 2 + h], b2r[x]);
                        ull e = encode(score, n0 + jb + 8 * ni + h);
                        if (e < bf) bf = e;
                        if (clur[x] == ciq && e < bp) bp = e;
                    }
#pragma unroll
                for (int o = 1; o <= 2; o <<= 1) {
                    ull tp = __shfl_xor_sync(0xffffffffu, bp, o);
                    ull tf = __shfl_xor_sync(0xffffffffu, bf, o);
                    if (tp < bp) bp = tp;
                    if (tf < bf) bf = tf;
                }
                if ((lane & 3) == 0) {
                    if (bp != ~0ULL) atomicMin(&redP[r], bp);
                    if (bf != ~0ULL) atomicMin(&redF[r], bf);
                }
            }
        }
    }
    __syncthreads();
    {
        ull p = redP[tid], f = redF[tid];
        if (p != ~0ULL) atomicMin(&g_bestP[tid], p);
        if (f != ~0ULL) atomicMin(&g_bestF[tid], f);
    }
}

// ---------------------------------------------------------------------------
__global__ void gather_kernel(const float* __restrict__ bank, float* __restrict__ out) {
    int b = blockIdx.x;
    ull e = g_bestP[b];
    if (e == ~0ULL) e = g_bestF[b];
    int idx = (e == ~0ULL) ? 0 : (int)(u32)(e & 0xffffffffu);
    const float4* src = (const float4*)(bank + (size_t)idx * DD);
    float4*       dst = (float4*)(out + (size_t)b * DD);
    dst[threadIdx.x] = src[threadIdx.x];
}

__global__ void noop_kernel() {}   // alignment: ncu captures launch #4 -> main_kernel

// ---------------------------------------------------------------------------
extern "C" void kernel_launch(void* const* d_in, const int* in_sizes, int n_in,
                              void* d_out, int out_size) {
    const float* feature = (const float*)d_in[0];
    const float* bank    = (const float*)d_in[1];
    const int*   cluL    = (const int*)d_in[2];
    const int*   clsL    = (const int*)d_in[3];
    const int*   cid     = (const int*)d_in[4];
    const int*   gtl     = (const int*)d_in[5];

    cudaFuncSetAttribute(main_kernel,
                         cudaFuncAttributeMaxDynamicSharedMemorySize, SMEM_TOTAL);

    prep_kernel<<<1, 256>>>(feature);                       // #1
    convert_kernel<<<(NBANK + 7) / 8, 256>>>(bank);         // #2
    noop_kernel<<<1, 32>>>();                               // #3
    main_kernel<<<NUM_TILES, 256, SMEM_TOTAL>>>(cluL, clsL, cid, gtl);  // #4 (ncu)
    gather_kernel<<<BQ, 64>>>(bank, (float*)d_out);         // #5
}

// round 7
// speedup vs baseline: 1.0427x; 1.0427x over previous
#include <cuda_runtime.h>
#include <cuda_bf16.h>

#define BQ 256
#define DD 256
#define NBANK 100000
#define NPAD 100096                    // padded rows (zero tail, safe cp.async)
#define TN 128
#define NUM_TILES ((NBANK + TN - 1) / TN)
#define NCH 8                          // K chunks of 32
#define KCH 32
#define SR 80                          // smem row stride bytes (64B data + 16B pad, 16B aligned)
#define THREADS 512

typedef unsigned long long ull;
typedef unsigned int u32;

// --------------- device scratch (no allocation allowed) ---------------------
__device__ ull   g_bestP[BQ];
__device__ ull   g_bestF[BQ];
__device__ uint4 g_Q[NCH][2][BQ][4];           // pre-split queries (256KB, L2-resident)
__device__ uint4 g_bankH[(size_t)NPAD * 32];   // bf16 hi image [n][256]
__device__ uint4 g_bankL[(size_t)NPAD * 32];   // bf16 lo image [n][256]
__device__ float g_b2[NPAD];

// --------------- smem layout (bytes) ----------------------------------------
#define QBUF  (2 * BQ * SR)                  // 40960 per buffer (hi+lo)
#define BBUF  (2 * TN * SR)                  // 20480 per buffer (hi+lo)
#define OFF_Q    0                           // [2 buf][2 split][256][SR]
#define OFF_B    (2 * QBUF)                  // 81920
#define OFF_RED  (OFF_B + 2 * BBUF)          // 122880
#define OFF_B2S  (OFF_RED + 2 * BQ * 8)      // 126976
#define OFF_SCLU (OFF_B2S + 512)
#define OFF_SCLS (OFF_SCLU + 512)
#define OFF_SCID (OFF_SCLS + 512)
#define OFF_SGT  (OFF_SCID + 1024)
#define SMEM_TOTAL (OFF_SGT + 1024)          // 130560

// --------------- helpers ------------------------------------------------------
__device__ __forceinline__ u32 smem_u32(const void* p) {
    u32 a;
    asm("{ .reg .u64 t; cvta.to.shared.u64 t, %1; cvt.u32.u64 %0, t; }" : "=r"(a) : "l"(p));
    return a;
}

#define LDSM_X4(r, addr) \
    asm volatile("ldmatrix.sync.aligned.m8n8.x4.shared.b16 {%0,%1,%2,%3}, [%4];" \
        : "=r"((r)[0]), "=r"((r)[1]), "=r"((r)[2]), "=r"((r)[3]) : "r"(addr))

#define MMA16816(d, a, b0, b1) \
    asm volatile("mma.sync.aligned.m16n8k16.row.col.f32.bf16.bf16.f32 " \
        "{%0,%1,%2,%3}, {%4,%5,%6,%7}, {%8,%9}, {%0,%1,%2,%3};" \
        : "+f"((d)[0]), "+f"((d)[1]), "+f"((d)[2]), "+f"((d)[3]) \
        : "r"((a)[0]), "r"((a)[1]), "r"((a)[2]), "r"((a)[3]), "r"(b0), "r"(b1))

#define CP_ASYNC16(dst, src) \
    asm volatile("cp.async.cg.shared.global [%0], [%1], 16;" :: "r"(dst), "l"(src) : "memory")
#define CP_COMMIT() asm volatile("cp.async.commit_group;" ::: "memory")
#define CP_WAIT0()  asm volatile("cp.async.wait_group 0;" ::: "memory")

// order-preserving float->u32 packed with index; ties -> lower index (argmin)
__device__ __forceinline__ ull encode(float f, int n) {
    u32 u = __float_as_uint(f);
    u = (u & 0x80000000u) ? ~u : (u | 0x80000000u);
    return ((ull)u << 32) | (u32)n;
}

__device__ __forceinline__ void split2(float a0, float a1, u32& H, u32& L) {
    __nv_bfloat16 h0 = __float2bfloat16(a0);
    __nv_bfloat16 h1 = __float2bfloat16(a1);
    __nv_bfloat16 l0 = __float2bfloat16(a0 - __bfloat162float(h0));
    __nv_bfloat16 l1 = __float2bfloat16(a1 - __bfloat162float(h1));
    H = (u32)__bfloat16_as_ushort(h0) | ((u32)__bfloat16_as_ushort(h1) << 16);
    L = (u32)__bfloat16_as_ushort(l0) | ((u32)__bfloat16_as_ushort(l1) << 16);
}

// ---------------------------------------------------------------------------
__global__ void prep_kernel(const float* __restrict__ feat) {
    int q = threadIdx.x;
    g_bestP[q] = ~0ULL;
    g_bestF[q] = ~0ULL;
    const float* row = feat + q * DD;
#pragma unroll
    for (int c = 0; c < NCH; ++c) {
#pragma unroll
        for (int i = 0; i < 4; ++i) {
            u32 H[4], L[4];
#pragma unroll
            for (int e = 0; e < 8; e += 2) {
                int k = c * KCH + i * 8 + e;
                split2(row[k], row[k + 1], H[e >> 1], L[e >> 1]);
            }
            g_Q[c][0][q][i] = make_uint4(H[0], H[1], H[2], H[3]);
            g_Q[c][1][q][i] = make_uint4(L[0], L[1], L[2], L[3]);
        }
    }
}

// ---------------------------------------------------------------------------
__global__ void __launch_bounds__(256) convert_kernel(const float* __restrict__ bank) {
    int row = blockIdx.x * 8 + (threadIdx.x >> 5);
    if (row >= NBANK) return;
    int lane = threadIdx.x & 31;
    const float4* src = (const float4*)(bank + (size_t)row * DD) + lane * 2;
    float4 v0 = src[0], v1 = src[1];
    float vv[8] = {v0.x, v0.y, v0.z, v0.w, v1.x, v1.y, v1.z, v1.w};
    u32 H[4], L[4];
    float s = 0.f;
#pragma unroll
    for (int e = 0; e < 8; e += 2) {
        s = fmaf(vv[e], vv[e], s);
        s = fmaf(vv[e + 1], vv[e + 1], s);
        split2(vv[e], vv[e + 1], H[e >> 1], L[e >> 1]);
    }
    g_bankH[(size_t)row * 32 + lane] = make_uint4(H[0], H[1], H[2], H[3]);
    g_bankL[(size_t)row * 32 + lane] = make_uint4(L[0], L[1], L[2], L[3]);
#pragma unroll
    for (int o = 16; o; o >>= 1) s += __shfl_xor_sync(0xffffffffu, s, o);
    if (lane == 0) g_b2[row] = s;
}

// ---------------------------------------------------------------------------
__device__ __forceinline__ void stage_chunk(u32 smb, int buf, int c, int tid, int n0) {
    // Q: 512 pieces (2 splits x 256 rows), 1 per thread (4x16B)
    {
        int row = tid & 255, split = tid >> 8;
        const uint4* s = &g_Q[c][split][row][0];
        u32 d = smb + OFF_Q + (u32)buf * QBUF + (u32)split * (BQ * SR) + (u32)row * SR;
#pragma unroll
        for (int i = 0; i < 4; ++i) CP_ASYNC16(d + 16 * i, s + i);
    }
    // B: 1024 pieces (2 splits x 128 rows x 4 segs), 2 per thread
#pragma unroll
    for (int p = 0; p < 2; ++p) {
        int idx = tid + THREADS * p;
        int split = idx >> 9, rw = (idx >> 2) & 127, seg = idx & 3;
        const uint4* src = (split ? g_bankL : g_bankH)
                           + (size_t)(n0 + rw) * 32 + c * 4 + seg;
        u32 dst = smb + OFF_B + (u32)buf * BBUF + (u32)split * (TN * SR)
                  + (u32)rw * SR + (u32)seg * 16;
        CP_ASYNC16(dst, src);
    }
}

// ---------------------------------------------------------------------------
// main: 128 bank rows x 256 queries per CTA, 512 threads (16 warps),
// warp tile 32q x 64n; 3-split bf16 HMMA + masked dual argmin.
// ---------------------------------------------------------------------------
__global__ void __launch_bounds__(THREADS, 1) main_kernel(
    const int* __restrict__ cluL, const int* __restrict__ clsL,
    const int* __restrict__ cid,  const int* __restrict__ gt)
{
    extern __shared__ char sm[];
    const u32 smb  = smem_u32(sm);
    const int tid  = threadIdx.x;
    const int lane = tid & 31;
    const int w    = tid >> 5;
    const int n0   = blockIdx.x * TN;

    ull*   redP = (ull*)(sm + OFF_RED);
    ull*   redF = redP + BQ;
    float* b2s  = (float*)(sm + OFF_B2S);
    int*   sClu = (int*)(sm + OFF_SCLU);
    int*   sCls = (int*)(sm + OFF_SCLS);
    int*   sCid = (int*)(sm + OFF_SCID);
    int*   sGt  = (int*)(sm + OFF_SGT);

    stage_chunk(smb, 0, 0, tid, n0);
    CP_COMMIT();

    if (tid < BQ) {
        redP[tid] = ~0ULL;
        redF[tid] = ~0ULL;
        sCid[tid] = cid[tid];
        sGt[tid]  = gt[tid];
    }
    if (tid < TN) {
        int n = n0 + tid;
        bool v = (n < NBANK);
        sClu[tid] = v ? cluL[n] : -1;
        sCls[tid] = v ? clsL[n] : 0x7fffffff;
        b2s[tid]  = v ? g_b2[n] : 0.f;
    }

    // Warp tiling: 8 q-groups x 2 n-halves. 32q x 64n per warp.
    const int q0 = (w & 7) * 32;
    const int nh = (w >> 3) * 64;

    float acc[2][8][4];
#pragma unroll
    for (int mi = 0; mi < 2; mi++)
#pragma unroll
        for (int nt = 0; nt < 8; nt++)
#pragma unroll
            for (int r = 0; r < 4; r++) acc[mi][nt][r] = 0.f;

    const u32 aRowOff = (u32)(q0 + (lane & 15)) * SR + (u32)(lane >> 4) * 16;
    const int bRow    = nh + ((lane >> 4) & 1) * 8 + (lane & 7);
    const u32 bColB   = ((lane >> 3) & 1) * 16;      // k-half byte offset

#pragma unroll 1
    for (int c = 0; c < NCH; ++c) {
        CP_WAIT0();
        __syncthreads();                              // chunk c resident
        if (c + 1 < NCH) { stage_chunk(smb, (c + 1) & 1, c + 1, tid, n0); CP_COMMIT(); }

        const int buf = c & 1;
        const u32 qH = smb + OFF_Q + (u32)buf * QBUF + aRowOff;
        const u32 qL = qH + (u32)BQ * SR;
        const u32 bH = smb + OFF_B + (u32)buf * BBUF;
        const u32 bL = bH + (u32)(TN * SR);
#pragma unroll
        for (int kk = 0; kk < KCH; kk += 16) {
            const u32 kb = (u32)kk * 2 + bColB;
            u32 aH[2][4];
#pragma unroll
            for (int mi = 0; mi < 2; mi++) LDSM_X4(aH[mi], qH + mi * 16 * SR + kk * 2);

            u32 bB[16];
#pragma unroll
            for (int p = 0; p < 4; p++)
                LDSM_X4(&bB[4 * p], bH + (u32)(bRow + p * 16) * SR + kb);
#pragma unroll
            for (int mi = 0; mi < 2; mi++)
#pragma unroll
                for (int nt = 0; nt < 8; nt++)
                    MMA16816(acc[mi][nt], aH[mi], bB[2 * nt], bB[2 * nt + 1]);

            u32 aL[2][4];
#pragma unroll
            for (int mi = 0; mi < 2; mi++) LDSM_X4(aL[mi], qL + mi * 16 * SR + kk * 2);
#pragma unroll
            for (int mi = 0; mi < 2; mi++)
#pragma unroll
                for (int nt = 0; nt < 8; nt++)
                    MMA16816(acc[mi][nt], aL[mi], bB[2 * nt], bB[2 * nt + 1]);

#pragma unroll
            for (int p = 0; p < 4; p++)
                LDSM_X4(&bB[4 * p], bL + (u32)(bRow + p * 16) * SR + kb);
#pragma unroll
            for (int mi = 0; mi < 2; mi++)
#pragma unroll
                for (int nt = 0; nt < 8; nt++)
                    MMA16816(acc[mi][nt], aH[mi], bB[2 * nt], bB[2 * nt + 1]);
        }
    }

    // ---- epilogue: masked dual argmin from HMMA fragments ----
    {
        const int jb = nh + 2 * (lane & 3);
        float b2r[16]; int clsr[16], clur[16]; bool val[16];
#pragma unroll
        for (int ni = 0; ni < 8; ni++)
#pragma unroll
            for (int h = 0; h < 2; h++) {
                int j = jb + 8 * ni + h, x = ni * 2 + h;
                b2r[x]  = b2s[j];
                clsr[x] = sCls[j];
                clur[x] = sClu[j];
                val[x]  = (n0 + j) < NBANK;
            }
#pragma unroll
        for (int mi = 0; mi < 2; mi++) {
#pragma unroll
            for (int half = 0; half < 2; half++) {
                int r = q0 + mi * 16 + (lane >> 2) + 8 * half;
                int gtq = sGt[r], ciq = sCid[r];
                ull bp = ~0ULL, bf = ~0ULL;
#pragma unroll
                for (int ni = 0; ni < 8; ni++)
#pragma unroll
                    for (int h = 0; h < 2; h++) {
                        int x = ni * 2 + h;
                        if (!val[x] || clsr[x] == gtq) continue;
                        float score = fmaf(-2.f, acc[mi][ni][half * 2 + h], b2r[x]);
                        ull e = encode(score, n0 + jb + 8 * ni + h);
                        if (e < bf) bf = e;
                        if (clur[x] == ciq && e < bp) bp = e;
                    }
#pragma unroll
                for (int o = 1; o <= 2; o <<= 1) {
                    ull tp = __shfl_xor_sync(0xffffffffu, bp, o);
                    ull tf = __shfl_xor_sync(0xffffffffu, bf, o);
                    if (tp < bp) bp = tp;
                    if (tf < bf) bf = tf;
                }
                if ((lane & 3) == 0) {
                    if (bp != ~0ULL) atomicMin(&redP[r], bp);
                    if (bf != ~0ULL) atomicMin(&redF[r], bf);
                }
            }
        }
    }
    __syncthreads();
    if (tid < BQ) {
        ull p = redP[tid], f = redF[tid];
        if (p != ~0ULL) atomicMin(&g_bestP[tid], p);
        if (f != ~0ULL) atomicMin(&g_bestF[tid], f);
    }
}

// ---------------------------------------------------------------------------
__global__ void gather_kernel(const float* __restrict__ bank, float* __restrict__ out) {
    int b = blockIdx.x;
    ull e = g_bestP[b];
    if (e == ~0ULL) e = g_bestF[b];
    int idx = (e == ~0ULL) ? 0 : (int)(u32)(e & 0xffffffffu);
    const float4* src = (const float4*)(bank + (size_t)idx * DD);
    float4*       dst = (float4*)(out + (size_t)b * DD);
    dst[threadIdx.x] = src[threadIdx.x];
}

__global__ void noop_kernel() {}   // alignment: ncu captures launch #4 -> main_kernel

// ---------------------------------------------------------------------------
extern "C" void kernel_launch(void* const* d_in, const int* in_sizes, int n_in,
                              void* d_out, int out_size) {
    const float* feature = (const float*)d_in[0];
    const float* bank    = (const float*)d_in[1];
    const int*   cluL    = (const int*)d_in[2];
    const int*   clsL    = (const int*)d_in[3];
    const int*   cid     = (const int*)d_in[4];
    const int*   gtl     = (const int*)d_in[5];

    cudaFuncSetAttribute(main_kernel,
                         cudaFuncAttributeMaxDynamicSharedMemorySize, SMEM_TOTAL);

    prep_kernel<<<1, 256>>>(feature);                       // #1
    convert_kernel<<<(NBANK + 7) / 8, 256>>>(bank);         // #2
    noop_kernel<<<1, 32>>>();                               // #3
    main_kernel<<<NUM_TILES, THREADS, SMEM_TOTAL>>>(cluL, clsL, cid, gtl);  // #4 (ncu)
    gather_kernel<<<BQ, 64>>>(bank, (float*)d_out);         // #5
}